// round 14
// baseline (speedup 1.0000x reference)
#include <cuda_runtime.h>
#include <cuda_fp16.h>
#include <cstdint>

// ---------------------------------------------------------------------------
// Fused gated-readout v9 (fp16 m16n8k16 via ldmatrix.x4, 2 CTAs/SM):
//   gate = sigmoid(MLP_g([h0;hT]))   512->128->256->128->256
//   val  = MLP_o(hT)                 256->128->256->128->256
//   out[b,:] = sum_n mask(b,n) * gate(b,n,:) * val(b,n,:)
// v9: X/Y/Z buffer rotation -> every layer writes a buffer disjoint from the
// one it reads (one sync beyond loop-tops).  Masked sigmoid goes straight
// from accumulators to smem Y (zero register residency) -> ~100 live regs,
// real ptxas scheduling headroom.  2 weight slots, depth-1 prefetch.
// ---------------------------------------------------------------------------

#define THREADS     256
#define NCHUNK      36
#define CHUNK_BYTES 16384

#define X_OFF       0                   // 32KB: h0 -> vL0-act -> vL1-act
#define Y_OFF       32768               // 32KB: hT -> masked sigmoid
#define Z_OFF       65536               // 16KB: gL0 -> gL2 -> vL2 acts
#define SLOT_OFF    81920               // 2 x 16384 weight slots
#define MASK_OFF    114688              // 64 fp32
#define SMEM_BYTES  114944

__device__ __align__(16) unsigned short g_wpack[NCHUNK * 8192];

// A-operand k-unit offset of each chunk (16B units into the swizzled row)
__constant__ int c_u0[NCHUNK] = {0,8,16,24, 0,8,16,24, 0,8,16,24,
                                 0,4,8,12,  0,8,16,24, 0,4,8,12,
                                 0,4,8,12,  0,8,16,24, 0,4,8,12};

__device__ __forceinline__ void hmma(float* d,
                                     uint32_t a0, uint32_t a1, uint32_t a2, uint32_t a3,
                                     uint32_t b0, uint32_t b1) {
    asm volatile(
        "mma.sync.aligned.m16n8k16.row.col.f32.f16.f16.f32 "
        "{%0,%1,%2,%3}, {%4,%5,%6,%7}, {%8,%9}, {%0,%1,%2,%3};"
        : "+f"(d[0]), "+f"(d[1]), "+f"(d[2]), "+f"(d[3])
        : "r"(a0), "r"(a1), "r"(a2), "r"(a3), "r"(b0), "r"(b1));
}

#define LDSM4(r, a) asm volatile( \
    "ldmatrix.sync.aligned.m8n8.x4.shared.b16 {%0,%1,%2,%3}, [%4];" \
    : "=r"((r)[0]), "=r"((r)[1]), "=r"((r)[2]), "=r"((r)[3]) : "r"(a))

// ---------------------------------------------------------------------------
// pack: chunk image = groups of 8 n-rows: [group][k-unit][n&7][16B]
// ---------------------------------------------------------------------------
__global__ void pack_kernel(const float* __restrict__ gW0, const float* __restrict__ gW1,
                            const float* __restrict__ gW2, const float* __restrict__ gW3,
                            const float* __restrict__ oW0, const float* __restrict__ oW1,
                            const float* __restrict__ oW2, const float* __restrict__ oW3) {
    int c = blockIdx.x;
    const float* W; int Nl, ks;
    if (c < 8)       { W = gW0; Nl = 128; ks = c * 64; }
    else if (c < 12) { W = oW0; Nl = 128; ks = (c - 8) * 64; }
    else if (c < 16) { W = gW1; Nl = 256; ks = (c - 12) * 32; }
    else if (c < 20) { W = gW2; Nl = 128; ks = (c - 16) * 64; }
    else if (c < 24) { W = gW3; Nl = 256; ks = (c - 20) * 32; }
    else if (c < 28) { W = oW1; Nl = 256; ks = (c - 24) * 32; }
    else if (c < 32) { W = oW2; Nl = 128; ks = (c - 28) * 64; }
    else             { W = oW3; Nl = 256; ks = (c - 32) * 32; }
    const int GSH = (Nl == 128) ? 512 : 256;
    unsigned short* dst = g_wpack + (size_t)c * 8192;
    for (int i = threadIdx.x; i < 8192; i += blockDim.x) {
        int n, kl;
        if (Nl == 128) { n = i >> 6; kl = i & 63; }
        else           { n = i >> 5; kl = i & 31; }
        int di = (n >> 3) * GSH + (kl >> 3) * 64 + (n & 7) * 8 + (kl & 7);
        dst[di] = __half_as_ushort(__float2half_rn(W[(size_t)(ks + kl) * Nl + n]));
    }
}

// ---------------------------------------------------------------------------
__device__ __forceinline__ void prefetch(char* smdst, int idx, int tid) {
    const char* src = (const char*)g_wpack + (size_t)idx * CHUNK_BYTES;
    uint32_t sb = (uint32_t)__cvta_generic_to_shared(smdst);
    #pragma unroll
    for (int i = 0; i < 4; i++) {
        int o = (tid + i * 256) * 16;
        asm volatile("cp.async.cg.shared.global [%0], [%1], 16;" :: "r"(sb + o), "l"(src + o));
    }
    asm volatile("cp.async.commit_group;");
}

// acc[2mt x NT x 4] += A[warp 32-row slice] @ W[warp n-slice] over KB k16 blocks
// PB = A-buffer row pitch in bytes
template <int KB, int NT, int GS, int PB>
__device__ __forceinline__ void mma_chunk(uint32_t abase, int u0, uint32_t wbase,
                                          float* acc, int mb, int nb, int lane) {
    const int sx  = lane & 7;
    const int hi  = lane >> 4;
    const int kb2 = (lane >> 3) & 1;
    const int dn  = sx + ((lane & 16) >> 1);
    const uint32_t arow = abase + (uint32_t)((mb + (lane & 15)) * PB);
    const uint32_t bln  = wbase + (uint32_t)((dn >> 3) * GS + (dn & 7) * 16 + kb2 * 128
                                             + (nb >> 3) * GS);
    #pragma unroll
    for (int kb = 0; kb < KB; kb++) {
        const uint32_t aoff = (uint32_t)((((u0 + 2 * kb + hi) ^ sx)) << 4);
        uint32_t a0[4], a1[4];
        LDSM4(a0, arow + aoff);
        LDSM4(a1, arow + 16u * PB + aoff);
        #pragma unroll
        for (int j = 0; j < NT / 2; j++) {
            uint32_t b[4];
            LDSM4(b, bln + (uint32_t)(2 * j * GS + kb * 256));
            hmma(acc + (2 * j) * 4,          a0[0], a0[1], a0[2], a0[3], b[0], b[1]);
            hmma(acc + (2 * j + 1) * 4,      a0[0], a0[1], a0[2], a0[3], b[2], b[3]);
            hmma(acc + (NT + 2 * j) * 4,     a1[0], a1[1], a1[2], a1[3], b[0], b[1]);
            hmma(acc + (NT + 2 * j + 1) * 4, a1[0], a1[1], a1[2], a1[3], b[2], b[3]);
        }
    }
}

// relu(acc + bias) -> swizzled fp16 A operand rows (pitch PB)
template <int NT, int PB>
__device__ __forceinline__ void store_act(char* __restrict__ dst, const float* acc,
                                          const float* __restrict__ bias,
                                          int mb, int nb, int g, int t) {
    #pragma unroll
    for (int nt = 0; nt < NT; nt++) {
        int c = nb + nt * 8 + 2 * t;
        float b0 = __ldg(bias + c), b1 = __ldg(bias + c + 1);
        int u = c >> 3, wb = (c & 7) * 2;
        #pragma unroll
        for (int mt = 0; mt < 2; mt++) {
            int id = (mt * NT + nt) * 4;
            int r0 = mb + mt * 16 + g, r1 = r0 + 8;
            *(__half2*)(dst + r0 * PB + ((u ^ (r0 & 7)) << 4) + wb) =
                __floats2half2_rn(fmaxf(acc[id] + b0, 0.f), fmaxf(acc[id + 1] + b1, 0.f));
            *(__half2*)(dst + r1 * PB + ((u ^ (r1 & 7)) << 4) + wb) =
                __floats2half2_rn(fmaxf(acc[id + 2] + b0, 0.f), fmaxf(acc[id + 3] + b1, 0.f));
        }
    }
}

// fp32 global tile -> swizzled fp16 buffer, pitch 512 (+ optional mask)
__device__ __forceinline__ void stage_in(char* __restrict__ buf, const float* __restrict__ X,
                                         size_t row0, float* mask_sh, int tid, bool domask) {
    int r = tid >> 2, q = tid & 3, sx = r & 7;
    const float4* src = (const float4*)(X + (row0 + r) * 256);
    float s = 0.f;
    #pragma unroll
    for (int i = 0; i < 8; i++) {
        int u = q * 8 + i;
        float4 v0 = src[2 * u], v1 = src[2 * u + 1];
        if (domask) s += v0.x + v0.y + v0.z + v0.w + v1.x + v1.y + v1.z + v1.w;
        union { uint4 u4; __half2 h[4]; } pk;
        pk.h[0] = __floats2half2_rn(v0.x, v0.y);
        pk.h[1] = __floats2half2_rn(v0.z, v0.w);
        pk.h[2] = __floats2half2_rn(v1.x, v1.y);
        pk.h[3] = __floats2half2_rn(v1.z, v1.w);
        *(uint4*)(buf + r * 512 + ((u ^ sx) << 4)) = pk.u4;
    }
    if (domask) {
        s += __shfl_xor_sync(0xffffffffu, s, 1);
        s += __shfl_xor_sync(0xffffffffu, s, 2);
        if (q == 0) mask_sh[r] = (s > 0.f) ? 1.f : 0.f;
    }
}

__device__ __forceinline__ void zero_n(float* a, int n) {
    #pragma unroll
    for (int i = 0; i < 64; i++) if (i < n) a[i] = 0.f;
}

__global__ void __launch_bounds__(THREADS, 2)
readout_kernel(const float* __restrict__ h0, const float* __restrict__ hT,
               const float* __restrict__ gb0, const float* __restrict__ gb1,
               const float* __restrict__ gb2, const float* __restrict__ gb3,
               const float* __restrict__ ob0, const float* __restrict__ ob1,
               const float* __restrict__ ob2, const float* __restrict__ ob3,
               float* __restrict__ out) {
    extern __shared__ __align__(16) char sm[];
    char*  bufX = sm + X_OFF;
    char*  bufY = sm + Y_OFF;
    char*  bufZ = sm + Z_OFF;
    float* mask_sh = (float*)(sm + MASK_OFF);
    const uint32_t smb = (uint32_t)__cvta_generic_to_shared(sm);
    const uint32_t aX = smb + X_OFF, aY = smb + Y_OFF, aZ = smb + Z_OFF;

    const int tid  = threadIdx.x;
    const int lane = tid & 31;
    const int w    = tid >> 5;
    const int wm   = w & 1, wn = w >> 1;          // 2 x 4 warp grid
    const int g    = lane >> 2, t = lane & 3;
    const int mb    = wm * 32;
    const int nb128 = wn * 32, nb256 = wn * 64;

    const size_t row0 = (size_t)blockIdx.x * 64;
    const int bidx = (int)(blockIdx.x >> 2);

    prefetch(sm + SLOT_OFF, 0, tid);
    stage_in(bufX, h0, row0, mask_sh, tid, true);

    float accA[32], accV[32], accB[64];
    zero_n(accA, 32); zero_n(accV, 32);

    for (int idx = 0; idx < NCHUNK; idx++) {
        __syncthreads();                              // orders acts + frees slot (idx-1)&1
        if (idx + 1 < NCHUNK)
            prefetch(sm + SLOT_OFF + ((idx + 1) & 1) * CHUNK_BYTES, idx + 1, tid);
        if (idx + 1 < NCHUNK) asm volatile("cp.async.wait_group 1;");
        else                  asm volatile("cp.async.wait_group 0;");

        const uint32_t ws = smb + SLOT_OFF + (uint32_t)((idx & 1) * CHUNK_BYTES);
        const int u0 = c_u0[idx];

        if (idx < 4)       mma_chunk<4,4,1024,512>(aX, u0, ws, accA, mb, nb128, lane); // gate L0a (h0)
        else if (idx < 8)  mma_chunk<4,4,1024,512>(aY, u0, ws, accA, mb, nb128, lane); // gate L0b (hT)
        else if (idx < 12) mma_chunk<4,4,1024,512>(aY, u0, ws, accV, mb, nb128, lane); // value L0 (hT)
        else if (idx < 16) mma_chunk<2,8,512,256> (aZ, u0, ws, accB, mb, nb256, lane); // gate L1
        else if (idx < 20) mma_chunk<4,4,1024,512>(aY, u0, ws, accA, mb, nb128, lane); // gate L2
        else if (idx < 24) mma_chunk<2,8,512,256> (aZ, u0, ws, accB, mb, nb256, lane); // gate L3
        else if (idx < 28) mma_chunk<2,8,512,512> (aX, u0, ws, accB, mb, nb256, lane); // value L1
        else if (idx < 32) mma_chunk<4,4,1024,512>(aX, u0, ws, accA, mb, nb128, lane); // value L2
        else               mma_chunk<2,8,512,256> (aZ, u0, ws, accB, mb, nb256, lane); // value L3

        // Epilogues: every store targets a buffer disjoint from the one the
        // current layer reads -> ordered by the next loop-top sync.
        if (idx == 3) {                                   // hT -> Y (untouched so far)
            stage_in(bufY, hT, row0, nullptr, tid, false);
        } else if (idx == 7) {                            // gate L0 act -> Z
            store_act<4,256>(bufZ, accA, gb0, mb, nb128, g, t);
        } else if (idx == 11) {                           // value L0 act -> X (h0 dead)
            store_act<4,512>(bufX, accV, ob0, mb, nb128, g, t);
            zero_n(accB, 64);
        } else if (idx == 15) {                           // gate L1 act -> Y? no: Y still
            store_act<8,512>(bufY, accB, gb1, mb, nb256, g, t);   // wait - see note below
            zero_n(accA, 32);
        } else if (idx == 19) {                           // gate L2 act -> Z
            store_act<4,256>(bufZ, accA, gb2, mb, nb128, g, t);
            zero_n(accB, 64);
        } else if (idx == 23) {                           // masked sigmoid -> Y (free since 19)
            #pragma unroll
            for (int nt = 0; nt < 8; nt++) {
                int c = nb256 + nt * 8 + 2 * t;
                float b0 = __ldg(gb3 + c), b1 = __ldg(gb3 + c + 1);
                int u = c >> 3, wb = (c & 7) * 2;
                #pragma unroll
                for (int mt = 0; mt < 2; mt++) {
                    int id = (mt * 8 + nt) * 4;
                    int r0 = mb + mt * 16 + g, r1 = r0 + 8;
                    float m0 = mask_sh[r0], m1 = mask_sh[r1];
                    float s0 = m0 / (1.f + __expf(-(accB[id]     + b0)));
                    float s1 = m0 / (1.f + __expf(-(accB[id + 1] + b1)));
                    float s2 = m1 / (1.f + __expf(-(accB[id + 2] + b0)));
                    float s3 = m1 / (1.f + __expf(-(accB[id + 3] + b1)));
                    *(__half2*)(bufY + r0 * 512 + ((u ^ (r0 & 7)) << 4) + wb) =
                        __floats2half2_rn(s0, s1);
                    *(__half2*)(bufY + r1 * 512 + ((u ^ (r1 & 7)) << 4) + wb) =
                        __floats2half2_rn(s2, s3);
                }
            }
            zero_n(accB, 64);
        } else if (idx == 27) {                           // value L1 act -> X (self-read: sync)
            __syncthreads();
            store_act<8,512>(bufX, accB, ob1, mb, nb256, g, t);
            zero_n(accA, 32);
        } else if (idx == 31) {                           // value L2 act -> Z (free since 23)
            store_act<4,256>(bufZ, accA, ob2, mb, nb128, g, t);
            zero_n(accB, 64);
        } else if (idx == 35) {                           // combine: sigmoid from Y, reduce
            #pragma unroll
            for (int nt = 0; nt < 8; nt++) {
                int c = nb256 + nt * 8 + 2 * t;
                float b0 = __ldg(ob3 + c), b1 = __ldg(ob3 + c + 1);
                int u = c >> 3, wb = (c & 7) * 2;
                float s0 = 0.f, s1 = 0.f;
                #pragma unroll
                for (int mt = 0; mt < 2; mt++) {
                    int id = (mt * 8 + nt) * 4;
                    int r0 = mb + mt * 16 + g, r1 = r0 + 8;
                    __half2 hg0 = *(__half2*)(bufY + r0 * 512 + ((u ^ (r0 & 7)) << 4) + wb);
                    __half2 hg1 = *(__half2*)(bufY + r1 * 512 + ((u ^ (r1 & 7)) << 4) + wb);
                    s0 += __low2float(hg0)  * (accB[id]     + b0)
                        + __low2float(hg1)  * (accB[id + 2] + b0);
                    s1 += __high2float(hg0) * (accB[id + 1] + b1)
                        + __high2float(hg1) * (accB[id + 3] + b1);
                }
                s0 += __shfl_xor_sync(0xffffffffu, s0, 4);
                s1 += __shfl_xor_sync(0xffffffffu, s1, 4);
                s0 += __shfl_xor_sync(0xffffffffu, s0, 8);
                s1 += __shfl_xor_sync(0xffffffffu, s1, 8);
                s0 += __shfl_xor_sync(0xffffffffu, s0, 16);
                s1 += __shfl_xor_sync(0xffffffffu, s1, 16);
                if (lane < 4) {
                    atomicAdd(&out[bidx * 256 + c],     s0);
                    atomicAdd(&out[bidx * 256 + c + 1], s1);
                }
            }
        }
    }
}

extern "C" void kernel_launch(void* const* d_in, const int* in_sizes, int n_in,
                              void* d_out, int out_size) {
    const float* h0  = (const float*)d_in[0];
    const float* hT  = (const float*)d_in[1];
    const float* gW0 = (const float*)d_in[2];  const float* gb0 = (const float*)d_in[3];
    const float* gW1 = (const float*)d_in[4];  const float* gb1 = (const float*)d_in[5];
    const float* gW2 = (const float*)d_in[6];  const float* gb2 = (const float*)d_in[7];
    const float* gW3 = (const float*)d_in[8];  const float* gb3 = (const float*)d_in[9];
    const float* oW0 = (const float*)d_in[10]; const float* ob0 = (const float*)d_in[11];
    const float* oW1 = (const float*)d_in[12]; const float* ob1 = (const float*)d_in[13];
    const float* oW2 = (const float*)d_in[14]; const float* ob2 = (const float*)d_in[15];
    const float* oW3 = (const float*)d_in[16]; const float* ob3 = (const float*)d_in[17];
    float* out = (float*)d_out;

    cudaFuncSetAttribute(readout_kernel,
                         cudaFuncAttributeMaxDynamicSharedMemorySize, SMEM_BYTES);
    cudaMemsetAsync(d_out, 0, (size_t)out_size * sizeof(float), 0);
    pack_kernel<<<NCHUNK, 256>>>(gW0, gW1, gW2, gW3, oW0, oW1, oW2, oW3);
    readout_kernel<<<2048, THREADS, SMEM_BYTES>>>(
        h0, hT, gb0, gb1, gb2, gb3, ob0, ob1, ob2, ob3, out);
}

// round 15
// speedup vs baseline: 1.0187x; 1.0187x over previous
#include <cuda_runtime.h>
#include <cuda_fp16.h>
#include <cstdint>

// ---------------------------------------------------------------------------
// Fused gated-readout v10 (fp16 m16n8k16 via ldmatrix.x4, 3 CTAs/SM):
//   gate = sigmoid(MLP_g([h0;hT]))   512->128->256->128->256
//   val  = MLP_o(hT)                 256->128->256->128->256
//   out[b,:] = sum_n mask(b,n) * gate(b,n,:) * val(b,n,:)
// v10: CTA = 32 rows (4096 CTAs).  Per-thread accumulators halve -> regs ~70
// -> __launch_bounds__(256,3) -> 24 warps/SM (+50% latency hiding).  Value-L0
// act parked in vpark (read directly by value L1), sigmoid in spark.
// ---------------------------------------------------------------------------

#define THREADS     256
#define NCHUNK      36
#define CHUNK_BYTES 16384

#define BUF_OFF     0                   // 32 x 512 = 16384 (main act buffer)
#define VPARK_OFF   16384               // 32 x 256 = 8192  (value-L0 act)
#define SPARK_OFF   24576               // 32 x 512 = 16384 (masked sigmoid)
#define SLOT_OFF    40960               // 2 x 16384 weight slots
#define MASK_OFF    73728               // 32 fp32
#define SMEM_BYTES  73856

__device__ __align__(16) unsigned short g_wpack[NCHUNK * 8192];

// A-operand k-unit offset of each chunk (16B units into the swizzled row)
__constant__ int c_u0[NCHUNK] = {0,8,16,24, 0,8,16,24, 0,8,16,24,
                                 0,4,8,12,  0,8,16,24, 0,4,8,12,
                                 0,4,8,12,  0,8,16,24, 0,4,8,12};

__device__ __forceinline__ void hmma(float* d,
                                     uint32_t a0, uint32_t a1, uint32_t a2, uint32_t a3,
                                     uint32_t b0, uint32_t b1) {
    asm volatile(
        "mma.sync.aligned.m16n8k16.row.col.f32.f16.f16.f32 "
        "{%0,%1,%2,%3}, {%4,%5,%6,%7}, {%8,%9}, {%0,%1,%2,%3};"
        : "+f"(d[0]), "+f"(d[1]), "+f"(d[2]), "+f"(d[3])
        : "r"(a0), "r"(a1), "r"(a2), "r"(a3), "r"(b0), "r"(b1));
}

#define LDSM4(r, a) asm volatile( \
    "ldmatrix.sync.aligned.m8n8.x4.shared.b16 {%0,%1,%2,%3}, [%4];" \
    : "=r"((r)[0]), "=r"((r)[1]), "=r"((r)[2]), "=r"((r)[3]) : "r"(a))

// ---------------------------------------------------------------------------
// pack: chunk image = groups of 8 n-rows: [group][k-unit][n&7][16B]
// (unchanged from v6 -- layout independent of CTA row count)
// ---------------------------------------------------------------------------
__global__ void pack_kernel(const float* __restrict__ gW0, const float* __restrict__ gW1,
                            const float* __restrict__ gW2, const float* __restrict__ gW3,
                            const float* __restrict__ oW0, const float* __restrict__ oW1,
                            const float* __restrict__ oW2, const float* __restrict__ oW3) {
    int c = blockIdx.x;
    const float* W; int Nl, ks;
    if (c < 8)       { W = gW0; Nl = 128; ks = c * 64; }
    else if (c < 12) { W = oW0; Nl = 128; ks = (c - 8) * 64; }
    else if (c < 16) { W = gW1; Nl = 256; ks = (c - 12) * 32; }
    else if (c < 20) { W = gW2; Nl = 128; ks = (c - 16) * 64; }
    else if (c < 24) { W = gW3; Nl = 256; ks = (c - 20) * 32; }
    else if (c < 28) { W = oW1; Nl = 256; ks = (c - 24) * 32; }
    else if (c < 32) { W = oW2; Nl = 128; ks = (c - 28) * 64; }
    else             { W = oW3; Nl = 256; ks = (c - 32) * 32; }
    const int GSH = (Nl == 128) ? 512 : 256;
    unsigned short* dst = g_wpack + (size_t)c * 8192;
    for (int i = threadIdx.x; i < 8192; i += blockDim.x) {
        int n, kl;
        if (Nl == 128) { n = i >> 6; kl = i & 63; }
        else           { n = i >> 5; kl = i & 31; }
        int di = (n >> 3) * GSH + (kl >> 3) * 64 + (n & 7) * 8 + (kl & 7);
        dst[di] = __half_as_ushort(__float2half_rn(W[(size_t)(ks + kl) * Nl + n]));
    }
}

// ---------------------------------------------------------------------------
__device__ __forceinline__ void prefetch(char* smdst, int idx, int tid) {
    const char* src = (const char*)g_wpack + (size_t)idx * CHUNK_BYTES;
    uint32_t sb = (uint32_t)__cvta_generic_to_shared(smdst);
    #pragma unroll
    for (int i = 0; i < 4; i++) {
        int o = (tid + i * 256) * 16;
        asm volatile("cp.async.cg.shared.global [%0], [%1], 16;" :: "r"(sb + o), "l"(src + o));
    }
    asm volatile("cp.async.commit_group;");
}

// acc[NT x 4] += A[warp 16-row slice] @ W[warp n-slice] over KB k16 blocks
// PB = A-buffer row pitch (bytes); GS = B chunk group stride (bytes)
template <int KB, int NT, int GS, int PB>
__device__ __forceinline__ void mma_chunk(uint32_t abase, int u0, uint32_t wbase,
                                          float* acc, int mb, int nb, int lane) {
    const int sx  = lane & 7;
    const int hi  = lane >> 4;
    const int kb2 = (lane >> 3) & 1;
    const int dn  = sx + ((lane & 16) >> 1);
    const uint32_t arow = abase + (uint32_t)((mb + (lane & 15)) * PB);
    const uint32_t bln  = wbase + (uint32_t)((dn >> 3) * GS + (dn & 7) * 16 + kb2 * 128
                                             + (nb >> 3) * GS);
    #pragma unroll
    for (int kb = 0; kb < KB; kb++) {
        const uint32_t aoff = (uint32_t)((((u0 + 2 * kb + hi) ^ sx)) << 4);
        uint32_t a[4];
        LDSM4(a, arow + aoff);
        #pragma unroll
        for (int j = 0; j < NT / 2; j++) {
            uint32_t b[4];
            LDSM4(b, bln + (uint32_t)(2 * j * GS + kb * 256));
            hmma(acc + (2 * j) * 4,     a[0], a[1], a[2], a[3], b[0], b[1]);
            hmma(acc + (2 * j + 1) * 4, a[0], a[1], a[2], a[3], b[2], b[3]);
        }
    }
}

// relu(acc + bias) -> swizzled fp16 A operand rows (pitch PB), 16-row warp slice
template <int NT, int PB>
__device__ __forceinline__ void store_act(char* __restrict__ dst, const float* acc,
                                          const float* __restrict__ bias,
                                          int mb, int nb, int g, int t) {
    #pragma unroll
    for (int nt = 0; nt < NT; nt++) {
        int c = nb + nt * 8 + 2 * t;
        float b0 = __ldg(bias + c), b1 = __ldg(bias + c + 1);
        int u = c >> 3, wb = (c & 7) * 2;
        int id = nt * 4;
        int r0 = mb + g, r1 = r0 + 8;
        *(__half2*)(dst + r0 * PB + ((u ^ (r0 & 7)) << 4) + wb) =
            __floats2half2_rn(fmaxf(acc[id] + b0, 0.f), fmaxf(acc[id + 1] + b1, 0.f));
        *(__half2*)(dst + r1 * PB + ((u ^ (r1 & 7)) << 4) + wb) =
            __floats2half2_rn(fmaxf(acc[id + 2] + b0, 0.f), fmaxf(acc[id + 3] + b1, 0.f));
    }
}

// fp32 global tile (32 rows x 256 cols) -> swizzled fp16 buf, pitch 512
__device__ __forceinline__ void stage_in(char* __restrict__ buf, const float* __restrict__ X,
                                         size_t row0, float* mask_sh, int tid, bool domask) {
    int r = tid >> 3, q = tid & 7, sx = r & 7;
    const float4* src = (const float4*)(X + (row0 + r) * 256);
    float s = 0.f;
    #pragma unroll
    for (int i = 0; i < 4; i++) {
        int u = q * 4 + i;                            // 0..31
        float4 v0 = src[2 * u], v1 = src[2 * u + 1];
        if (domask) s += v0.x + v0.y + v0.z + v0.w + v1.x + v1.y + v1.z + v1.w;
        union { uint4 u4; __half2 h[4]; } pk;
        pk.h[0] = __floats2half2_rn(v0.x, v0.y);
        pk.h[1] = __floats2half2_rn(v0.z, v0.w);
        pk.h[2] = __floats2half2_rn(v1.x, v1.y);
        pk.h[3] = __floats2half2_rn(v1.z, v1.w);
        *(uint4*)(buf + r * 512 + ((u ^ sx) << 4)) = pk.u4;
    }
    if (domask) {
        s += __shfl_xor_sync(0xffffffffu, s, 1);
        s += __shfl_xor_sync(0xffffffffu, s, 2);
        s += __shfl_xor_sync(0xffffffffu, s, 4);
        if (q == 0) mask_sh[r] = (s > 0.f) ? 1.f : 0.f;
    }
}

__device__ __forceinline__ void zero_n(float* a, int n) {
    #pragma unroll
    for (int i = 0; i < 32; i++) if (i < n) a[i] = 0.f;
}

__global__ void __launch_bounds__(THREADS, 3)
readout_kernel(const float* __restrict__ h0, const float* __restrict__ hT,
               const float* __restrict__ gb0, const float* __restrict__ gb1,
               const float* __restrict__ gb2, const float* __restrict__ gb3,
               const float* __restrict__ ob0, const float* __restrict__ ob1,
               const float* __restrict__ ob2, const float* __restrict__ ob3,
               float* __restrict__ out) {
    extern __shared__ __align__(16) char sm[];
    char*  buf   = sm + BUF_OFF;
    char*  vpark = sm + VPARK_OFF;
    char*  spark = sm + SPARK_OFF;
    float* mask_sh = (float*)(sm + MASK_OFF);
    const uint32_t smb = (uint32_t)__cvta_generic_to_shared(sm);
    const uint32_t aBUF = smb + BUF_OFF, aVP = smb + VPARK_OFF;

    const int tid  = threadIdx.x;
    const int lane = tid & 31;
    const int w    = tid >> 5;
    const int wm   = w & 1, wn = w >> 1;          // 2 x 4 warp grid
    const int g    = lane >> 2, t = lane & 3;
    const int mb    = wm * 16;                    // warp row base (16-row slice)
    const int nb128 = wn * 32, nb256 = wn * 64;

    const size_t row0 = (size_t)blockIdx.x * 32;
    const int bidx = (int)(blockIdx.x >> 3);      // 8 CTAs per batch row

    prefetch(sm + SLOT_OFF, 0, tid);
    stage_in(buf, h0, row0, mask_sh, tid, true);

    float accA[16], accV[16], accB[32];
    zero_n(accA, 16); zero_n(accV, 16);

    for (int idx = 0; idx < NCHUNK; idx++) {
        __syncthreads();                          // epi stores + slot (idx+1)&1 freed
        if (idx + 1 < NCHUNK) {
            prefetch(sm + SLOT_OFF + ((idx + 1) & 1) * CHUNK_BYTES, idx + 1, tid);
            asm volatile("cp.async.wait_group 1;");
        } else {
            asm volatile("cp.async.wait_group 0;");
        }

        const uint32_t ws = smb + SLOT_OFF + (uint32_t)((idx & 1) * CHUNK_BYTES);
        const int u0 = c_u0[idx];

        if (idx < 8)       mma_chunk<4,4,1024,512>(aBUF, u0, ws, accA, mb, nb128, lane); // gate L0
        else if (idx < 12) mma_chunk<4,4,1024,512>(aBUF, u0, ws, accV, mb, nb128, lane); // value L0
        else if (idx < 16) mma_chunk<2,8,512,512> (aBUF, u0, ws, accB, mb, nb256, lane); // gate L1
        else if (idx < 20) mma_chunk<4,4,1024,512>(aBUF, u0, ws, accA, mb, nb128, lane); // gate L2
        else if (idx < 24) mma_chunk<2,8,512,512> (aBUF, u0, ws, accB, mb, nb256, lane); // gate L3
        else if (idx < 28) mma_chunk<2,8,512,256> (aVP,  u0, ws, accB, mb, nb256, lane); // value L1
        else if (idx < 32) mma_chunk<4,4,1024,512>(aBUF, u0, ws, accA, mb, nb128, lane); // value L2
        else               mma_chunk<2,8,512,512> (aBUF, u0, ws, accB, mb, nb256, lane); // value L3

        if (idx == 3) {                                   // hT restage (self: sync)
            __syncthreads();
            stage_in(buf, hT, row0, nullptr, tid, false);
        } else if (idx == 11) {                           // gate L0 act -> buf, value L0 -> vpark
            __syncthreads();
            store_act<4,512>(buf,   accA, gb0, mb, nb128, g, t);
            store_act<4,256>(vpark, accV, ob0, mb, nb128, g, t);
            zero_n(accB, 32);
        } else if (idx == 15) {                           // gate L1 act -> buf (self: sync)
            __syncthreads();
            store_act<8,512>(buf, accB, gb1, mb, nb256, g, t);
            zero_n(accA, 16);
        } else if (idx == 19) {                           // gate L2 act -> buf (self: sync)
            __syncthreads();
            store_act<4,512>(buf, accA, gb2, mb, nb128, g, t);
            zero_n(accB, 32);
        } else if (idx == 23) {                           // masked sigmoid -> spark (no sync)
            #pragma unroll
            for (int nt = 0; nt < 8; nt++) {
                int c = nb256 + nt * 8 + 2 * t;
                float b0 = __ldg(gb3 + c), b1 = __ldg(gb3 + c + 1);
                int u = c >> 3, wb = (c & 7) * 2;
                int id = nt * 4;
                int r0 = mb + g, r1 = r0 + 8;
                float m0 = mask_sh[r0], m1 = mask_sh[r1];
                float s0 = m0 / (1.f + __expf(-(accB[id]     + b0)));
                float s1 = m0 / (1.f + __expf(-(accB[id + 1] + b1)));
                float s2 = m1 / (1.f + __expf(-(accB[id + 2] + b0)));
                float s3 = m1 / (1.f + __expf(-(accB[id + 3] + b1)));
                *(__half2*)(spark + r0 * 512 + ((u ^ (r0 & 7)) << 4) + wb) =
                    __floats2half2_rn(s0, s1);
                *(__half2*)(spark + r1 * 512 + ((u ^ (r1 & 7)) << 4) + wb) =
                    __floats2half2_rn(s2, s3);
            }
            zero_n(accB, 32);
        } else if (idx == 27) {                           // value L1 act -> buf
            // buf last read at idx 23 (gate L3); idx 24-27 read vpark ->
            // loop-top syncs at 24..27 already ordered those reads. No sync.
            store_act<8,512>(buf, accB, ob1, mb, nb256, g, t);
            zero_n(accA, 16);
        } else if (idx == 31) {                           // value L2 act -> buf (self: sync)
            __syncthreads();
            store_act<4,512>(buf, accA, ob2, mb, nb128, g, t);
            zero_n(accB, 32);
        } else if (idx == 35) {                           // combine + node reduction
            #pragma unroll
            for (int nt = 0; nt < 8; nt++) {
                int c = nb256 + nt * 8 + 2 * t;
                float b0 = __ldg(ob3 + c), b1 = __ldg(ob3 + c + 1);
                int u = c >> 3, wb = (c & 7) * 2;
                int id = nt * 4;
                int r0 = mb + g, r1 = r0 + 8;
                __half2 hg0 = *(__half2*)(spark + r0 * 512 + ((u ^ (r0 & 7)) << 4) + wb);
                __half2 hg1 = *(__half2*)(spark + r1 * 512 + ((u ^ (r1 & 7)) << 4) + wb);
                float s0 = __low2float(hg0)  * (accB[id]     + b0)
                         + __low2float(hg1)  * (accB[id + 2] + b0);
                float s1 = __high2float(hg0) * (accB[id + 1] + b1)
                         + __high2float(hg1) * (accB[id + 3] + b1);
                s0 += __shfl_xor_sync(0xffffffffu, s0, 4);
                s1 += __shfl_xor_sync(0xffffffffu, s1, 4);
                s0 += __shfl_xor_sync(0xffffffffu, s0, 8);
                s1 += __shfl_xor_sync(0xffffffffu, s1, 8);
                s0 += __shfl_xor_sync(0xffffffffu, s0, 16);
                s1 += __shfl_xor_sync(0xffffffffu, s1, 16);
                if (lane < 4) {
                    atomicAdd(&out[bidx * 256 + c],     s0);
                    atomicAdd(&out[bidx * 256 + c + 1], s1);
                }
            }
        }
    }
}

extern "C" void kernel_launch(void* const* d_in, const int* in_sizes, int n_in,
                              void* d_out, int out_size) {
    const float* h0  = (const float*)d_in[0];
    const float* hT  = (const float*)d_in[1];
    const float* gW0 = (const float*)d_in[2];  const float* gb0 = (const float*)d_in[3];
    const float* gW1 = (const float*)d_in[4];  const float* gb1 = (const float*)d_in[5];
    const float* gW2 = (const float*)d_in[6];  const float* gb2 = (const float*)d_in[7];
    const float* gW3 = (const float*)d_in[8];  const float* gb3 = (const float*)d_in[9];
    const float* oW0 = (const float*)d_in[10]; const float* ob0 = (const float*)d_in[11];
    const float* oW1 = (const float*)d_in[12]; const float* ob1 = (const float*)d_in[13];
    const float* oW2 = (const float*)d_in[14]; const float* ob2 = (const float*)d_in[15];
    const float* oW3 = (const float*)d_in[16]; const float* ob3 = (const float*)d_in[17];
    float* out = (float*)d_out;

    cudaFuncSetAttribute(readout_kernel,
                         cudaFuncAttributeMaxDynamicSharedMemorySize, SMEM_BYTES);
    cudaMemsetAsync(d_out, 0, (size_t)out_size * sizeof(float), 0);
    pack_kernel<<<NCHUNK, 256>>>(gW0, gW1, gW2, gW3, oW0, oW1, oW2, oW3);
    readout_kernel<<<4096, THREADS, SMEM_BYTES>>>(
        h0, hT, gb0, gb1, gb2, gb3, ob0, ob1, ob2, ob3, out);
}

// round 16
// speedup vs baseline: 1.2217x; 1.1992x over previous
#include <cuda_runtime.h>
#include <cuda_fp16.h>
#include <cstdint>

// ---------------------------------------------------------------------------
// Fused gated-readout v11 (fp16 m16n8k16 via ldmatrix.x4, 2 CTAs/SM):
//   gate = sigmoid(MLP_g([h0;hT]))   512->128->256->128->256
//   val  = MLP_o(hT)                 256->128->256->128->256
//   out[b,:] = sum_n mask(b,n) * gate(b,n,:) * val(b,n,:)
// v11 = v6 mma core + per-warp-pair weight streaming: weights pre-packed as
// per-(chunk, n-slice) 4KB blobs; each 2-warp column pair cp.asyncs its own
// slice into a private 2-phase slot and syncs with a named barrier (64 thr).
// Block-wide __syncthreads only at the 7 activation boundaries (~15 vs 36).
// ---------------------------------------------------------------------------

#define THREADS     256
#define NCHUNK      36

#define BUF_OFF     0                   // 64 x 512 act buffer (swizzled)
#define GP_OFF      32768               // 64 x 512 park (value act / sigmoid)
#define SLOT_OFF    65536               // 4 wn x 2 phase x 4096
#define MASK_OFF    98304               // 64 fp32
#define SMEM_BYTES  98560

__device__ __align__(16) unsigned short g_wpack[NCHUNK * 8192];

// A-operand k-unit offset of each chunk (16B units into the swizzled row)
__constant__ int c_u0[NCHUNK] = {0,8,16,24, 0,8,16,24, 0,8,16,24,
                                 0,4,8,12,  0,8,16,24, 0,4,8,12,
                                 0,4,8,12,  0,8,16,24, 0,4,8,12};

__device__ __forceinline__ void hmma(float* d,
                                     uint32_t a0, uint32_t a1, uint32_t a2, uint32_t a3,
                                     uint32_t b0, uint32_t b1) {
    asm volatile(
        "mma.sync.aligned.m16n8k16.row.col.f32.f16.f16.f32 "
        "{%0,%1,%2,%3}, {%4,%5,%6,%7}, {%8,%9}, {%0,%1,%2,%3};"
        : "+f"(d[0]), "+f"(d[1]), "+f"(d[2]), "+f"(d[3])
        : "r"(a0), "r"(a1), "r"(a2), "r"(a3), "r"(b0), "r"(b1));
}

#define LDSM4(r, a) asm volatile( \
    "ldmatrix.sync.aligned.m8n8.x4.shared.b16 {%0,%1,%2,%3}, [%4];" \
    : "=r"((r)[0]), "=r"((r)[1]), "=r"((r)[2]), "=r"((r)[3]) : "r"(a))

// ---------------------------------------------------------------------------
// pack: chunk image = 4 slices of 4KB (one per warp-pair n-slice).
// Slice layout: groups of 8 n-rows: [group][k-unit][n&7][16B].
// ---------------------------------------------------------------------------
__global__ void pack_kernel(const float* __restrict__ gW0, const float* __restrict__ gW1,
                            const float* __restrict__ gW2, const float* __restrict__ gW3,
                            const float* __restrict__ oW0, const float* __restrict__ oW1,
                            const float* __restrict__ oW2, const float* __restrict__ oW3) {
    int c = blockIdx.x;
    const float* W; int Nl, ks;
    if (c < 8)       { W = gW0; Nl = 128; ks = c * 64; }
    else if (c < 12) { W = oW0; Nl = 128; ks = (c - 8) * 64; }
    else if (c < 16) { W = gW1; Nl = 256; ks = (c - 12) * 32; }
    else if (c < 20) { W = gW2; Nl = 128; ks = (c - 16) * 64; }
    else if (c < 24) { W = gW3; Nl = 256; ks = (c - 20) * 32; }
    else if (c < 28) { W = oW1; Nl = 256; ks = (c - 24) * 32; }
    else if (c < 32) { W = oW2; Nl = 128; ks = (c - 28) * 64; }
    else             { W = oW3; Nl = 256; ks = (c - 32) * 32; }
    unsigned short* dst = g_wpack + (size_t)c * 8192;
    for (int i = threadIdx.x; i < 8192; i += blockDim.x) {
        int s = i >> 11;              // n-slice (warp-pair)
        int r = i & 2047;
        int n, kl;
        if (Nl == 128) {              // slice = 32 n x 64 k, 4 groups of 1KB
            int gi = r >> 9, r2 = r & 511;
            n  = s * 32 + gi * 8 + ((r2 >> 3) & 7);
            kl = (r2 >> 6) * 8 + (r2 & 7);
        } else {                      // slice = 64 n x 32 k, 8 groups of 512B
            int gi = r >> 8, r2 = r & 255;
            n  = s * 64 + gi * 8 + ((r2 >> 3) & 7);
            kl = (r2 >> 6) * 8 + (r2 & 7);
        }
        dst[i] = __half_as_ushort(__float2half_rn(W[(size_t)(ks + kl) * Nl + n]));
    }
}

// ---------------------------------------------------------------------------
// per-warp prefetch: this warp's half (2KB) of its pair's 4KB slice
// ---------------------------------------------------------------------------
__device__ __forceinline__ void prefetch_slice(char* sm, int idx, int phase,
                                               int wn, int wm, int lane) {
    const char* src = (const char*)g_wpack + (size_t)idx * 16384 + wn * 4096 + wm * 2048;
    uint32_t sb = (uint32_t)__cvta_generic_to_shared(
        sm + SLOT_OFF + wn * 8192 + phase * 4096 + wm * 2048);
    #pragma unroll
    for (int i = 0; i < 4; i++) {
        int o = (lane + i * 32) * 16;
        asm volatile("cp.async.cg.shared.global [%0], [%1], 16;" :: "r"(sb + o), "l"(src + o));
    }
    asm volatile("cp.async.commit_group;");
}

// acc[2mt x NT x 4] += A[warp 32-row slice] @ W[this pair's n-slice]
template <int KB, int NT, int GS>
__device__ __forceinline__ void mma_chunk(uint32_t abase, int u0, uint32_t wbase,
                                          float* acc, int mb, int lane) {
    const int sx  = lane & 7;
    const int hi  = lane >> 4;
    const int kb2 = (lane >> 3) & 1;
    const int dn  = sx + ((lane & 16) >> 1);
    const uint32_t arow = abase + (uint32_t)((mb + (lane & 15)) * 512);
    const uint32_t bln  = wbase + (uint32_t)((dn >> 3) * GS + (dn & 7) * 16 + kb2 * 128);
    #pragma unroll
    for (int kb = 0; kb < KB; kb++) {
        const uint32_t aoff = (uint32_t)((((u0 + 2 * kb + hi) ^ sx)) << 4);
        uint32_t a0[4], a1[4];
        LDSM4(a0, arow + aoff);
        LDSM4(a1, arow + 16u * 512 + aoff);
        #pragma unroll
        for (int j = 0; j < NT / 2; j++) {
            uint32_t b[4];
            LDSM4(b, bln + (uint32_t)(2 * j * GS + kb * 256));
            hmma(acc + (2 * j) * 4,          a0[0], a0[1], a0[2], a0[3], b[0], b[1]);
            hmma(acc + (2 * j + 1) * 4,      a0[0], a0[1], a0[2], a0[3], b[2], b[3]);
            hmma(acc + (NT + 2 * j) * 4,     a1[0], a1[1], a1[2], a1[3], b[0], b[1]);
            hmma(acc + (NT + 2 * j + 1) * 4, a1[0], a1[1], a1[2], a1[3], b[2], b[3]);
        }
    }
}

// relu(acc + bias) -> swizzled fp16 A operand rows (pitch 512)
template <int NT>
__device__ __forceinline__ void store_act(char* __restrict__ dst, const float* acc,
                                          const float* __restrict__ bias,
                                          int mb, int nb, int g, int t) {
    #pragma unroll
    for (int nt = 0; nt < NT; nt++) {
        int c = nb + nt * 8 + 2 * t;
        float b0 = __ldg(bias + c), b1 = __ldg(bias + c + 1);
        int u = c >> 3, wb = (c & 7) * 2;
        #pragma unroll
        for (int mt = 0; mt < 2; mt++) {
            int id = (mt * NT + nt) * 4;
            int r0 = mb + mt * 16 + g, r1 = r0 + 8;
            *(__half2*)(dst + r0 * 512 + ((u ^ (r0 & 7)) << 4) + wb) =
                __floats2half2_rn(fmaxf(acc[id] + b0, 0.f), fmaxf(acc[id + 1] + b1, 0.f));
            *(__half2*)(dst + r1 * 512 + ((u ^ (r1 & 7)) << 4) + wb) =
                __floats2half2_rn(fmaxf(acc[id + 2] + b0, 0.f), fmaxf(acc[id + 3] + b1, 0.f));
        }
    }
}

// fp32 global tile -> swizzled fp16 A buffer (+ optional mask)
__device__ __forceinline__ void stage_in(char* __restrict__ buf, const float* __restrict__ X,
                                         size_t row0, float* mask_sh, int tid, bool domask) {
    int r = tid >> 2, q = tid & 3, sx = r & 7;
    const float4* src = (const float4*)(X + (row0 + r) * 256);
    float s = 0.f;
    #pragma unroll
    for (int i = 0; i < 8; i++) {
        int u = q * 8 + i;
        float4 v0 = src[2 * u], v1 = src[2 * u + 1];
        if (domask) s += v0.x + v0.y + v0.z + v0.w + v1.x + v1.y + v1.z + v1.w;
        union { uint4 u4; __half2 h[4]; } pk;
        pk.h[0] = __floats2half2_rn(v0.x, v0.y);
        pk.h[1] = __floats2half2_rn(v0.z, v0.w);
        pk.h[2] = __floats2half2_rn(v1.x, v1.y);
        pk.h[3] = __floats2half2_rn(v1.z, v1.w);
        *(uint4*)(buf + r * 512 + ((u ^ sx) << 4)) = pk.u4;
    }
    if (domask) {
        s += __shfl_xor_sync(0xffffffffu, s, 1);
        s += __shfl_xor_sync(0xffffffffu, s, 2);
        if (q == 0) mask_sh[r] = (s > 0.f) ? 1.f : 0.f;
    }
}

__device__ __forceinline__ void zero_n(float* a, int n) {
    #pragma unroll
    for (int i = 0; i < 64; i++) if (i < n) a[i] = 0.f;
}

__global__ void __launch_bounds__(THREADS, 2)
readout_kernel(const float* __restrict__ h0, const float* __restrict__ hT,
               const float* __restrict__ gb0, const float* __restrict__ gb1,
               const float* __restrict__ gb2, const float* __restrict__ gb3,
               const float* __restrict__ ob0, const float* __restrict__ ob1,
               const float* __restrict__ ob2, const float* __restrict__ ob3,
               float* __restrict__ out) {
    extern __shared__ __align__(16) char sm[];
    char*  buf   = sm + BUF_OFF;
    char*  gpark = sm + GP_OFF;
    float* mask_sh = (float*)(sm + MASK_OFF);
    const uint32_t smb = (uint32_t)__cvta_generic_to_shared(sm);
    const uint32_t aBUF = smb + BUF_OFF;

    const int tid  = threadIdx.x;
    const int lane = tid & 31;
    const int w    = tid >> 5;
    const int wm   = w & 1, wn = w >> 1;          // 2 x 4 warp grid
    const int g    = lane >> 2, t = lane & 3;
    const int mb    = wm * 32;
    const int nb128 = wn * 32, nb256 = wn * 64;
    const int barid = 1 + wn;                     // named barrier per pair

    const size_t row0 = (size_t)blockIdx.x * 64;
    const int bidx = (int)(blockIdx.x >> 2);

    prefetch_slice(sm, 0, 0, wn, wm, lane);
    stage_in(buf, h0, row0, mask_sh, tid, true);
    __syncthreads();

    float accA[32], accV[32], accB[64];
    zero_n(accA, 32); zero_n(accV, 32);

    for (int idx = 0; idx < NCHUNK; idx++) {
        const int phase = idx & 1;
        asm volatile("cp.async.wait_group 0;");                  // own slice landed
        asm volatile("bar.sync %0, 64;" :: "r"(barid) : "memory"); // pair rendezvous
        if (idx + 1 < NCHUNK)
            prefetch_slice(sm, idx + 1, phase ^ 1, wn, wm, lane);

        const uint32_t ws = smb + SLOT_OFF + (uint32_t)(wn * 8192 + phase * 4096);
        const int u0 = c_u0[idx];

        if (idx < 8)       mma_chunk<4,4,1024>(aBUF, u0, ws, accA, mb, lane); // gate L0
        else if (idx < 12) mma_chunk<4,4,1024>(aBUF, u0, ws, accV, mb, lane); // value L0
        else if (idx < 16) mma_chunk<2,8,512> (aBUF, u0, ws, accB, mb, lane); // gate L1
        else if (idx < 20) mma_chunk<4,4,1024>(aBUF, u0, ws, accA, mb, lane); // gate L2
        else if (idx < 24) mma_chunk<2,8,512> (aBUF, u0, ws, accB, mb, lane); // gate L3
        else if (idx < 28) mma_chunk<2,8,512> (aBUF, u0, ws, accB, mb, lane); // value L1
        else if (idx < 32) mma_chunk<4,4,1024>(aBUF, u0, ws, accA, mb, lane); // value L2
        else               mma_chunk<2,8,512> (aBUF, u0, ws, accB, mb, lane); // value L3

        if (idx == 3) {                                   // h0 -> hT restage
            __syncthreads();
            stage_in(buf, hT, row0, nullptr, tid, false);
            __syncthreads();
        } else if (idx == 11) {                           // gate act -> buf, value act -> park
            __syncthreads();
            store_act<4>(buf,   accA, gb0, mb, nb128, g, t);
            store_act<4>(gpark, accV, ob0, mb, nb128, g, t);
            __syncthreads();
            zero_n(accB, 64);
        } else if (idx == 15) {
            __syncthreads();
            store_act<8>(buf, accB, gb1, mb, nb256, g, t);
            __syncthreads();
            zero_n(accA, 32);
        } else if (idx == 19) {
            __syncthreads();
            store_act<4>(buf, accA, gb2, mb, nb128, g, t);
            __syncthreads();
            zero_n(accB, 64);
        } else if (idx == 23) {
            __syncthreads();
            // parked value act (units 0-15, swizzle-identical) -> buf
            #pragma unroll
            for (int j = 0; j < 4; j++) {
                int tt = tid + j * 256;
                int r = tt >> 4, off = (tt & 15) * 16;
                *(float4*)(buf + r * 512 + off) = *(const float4*)(gpark + r * 512 + off);
            }
            __syncthreads();
            // sigmoid(gate L3 + gb3) -> gpark (fp16, swizzled)
            #pragma unroll
            for (int nt = 0; nt < 8; nt++) {
                int c = nb256 + nt * 8 + 2 * t;
                float b0 = __ldg(gb3 + c), b1 = __ldg(gb3 + c + 1);
                int u = c >> 3, wb = (c & 7) * 2;
                #pragma unroll
                for (int mt = 0; mt < 2; mt++) {
                    int id = (mt * 8 + nt) * 4;
                    int r0 = mb + mt * 16 + g, r1 = r0 + 8;
                    float s0 = 1.f / (1.f + __expf(-(accB[id]     + b0)));
                    float s1 = 1.f / (1.f + __expf(-(accB[id + 1] + b1)));
                    float s2 = 1.f / (1.f + __expf(-(accB[id + 2] + b0)));
                    float s3 = 1.f / (1.f + __expf(-(accB[id + 3] + b1)));
                    *(__half2*)(gpark + r0 * 512 + ((u ^ (r0 & 7)) << 4) + wb) =
                        __floats2half2_rn(s0, s1);
                    *(__half2*)(gpark + r1 * 512 + ((u ^ (r1 & 7)) << 4) + wb) =
                        __floats2half2_rn(s2, s3);
                }
            }
            __syncthreads();
            zero_n(accB, 64);
        } else if (idx == 27) {
            __syncthreads();
            store_act<8>(buf, accB, ob1, mb, nb256, g, t);
            __syncthreads();
            zero_n(accA, 32);
        } else if (idx == 31) {
            __syncthreads();
            store_act<4>(buf, accA, ob2, mb, nb128, g, t);
            __syncthreads();
            zero_n(accB, 64);
        } else if (idx == 35) {                           // combine + node reduction
            #pragma unroll
            for (int nt = 0; nt < 8; nt++) {
                int c = nb256 + nt * 8 + 2 * t;
                float b0 = __ldg(ob3 + c), b1 = __ldg(ob3 + c + 1);
                int u = c >> 3, wb = (c & 7) * 2;
                float s0 = 0.f, s1 = 0.f;
                #pragma unroll
                for (int mt = 0; mt < 2; mt++) {
                    int id = (mt * 8 + nt) * 4;
                    int r0 = mb + mt * 16 + g, r1 = r0 + 8;
                    __half2 hg0 = *(__half2*)(gpark + r0 * 512 + ((u ^ (r0 & 7)) << 4) + wb);
                    __half2 hg1 = *(__half2*)(gpark + r1 * 512 + ((u ^ (r1 & 7)) << 4) + wb);
                    float m0 = mask_sh[r0], m1 = mask_sh[r1];
                    s0 += m0 * __low2float(hg0)  * (accB[id]     + b0)
                        + m1 * __low2float(hg1)  * (accB[id + 2] + b0);
                    s1 += m0 * __high2float(hg0) * (accB[id + 1] + b1)
                        + m1 * __high2float(hg1) * (accB[id + 3] + b1);
                }
                s0 += __shfl_xor_sync(0xffffffffu, s0, 4);
                s1 += __shfl_xor_sync(0xffffffffu, s1, 4);
                s0 += __shfl_xor_sync(0xffffffffu, s0, 8);
                s1 += __shfl_xor_sync(0xffffffffu, s1, 8);
                s0 += __shfl_xor_sync(0xffffffffu, s0, 16);
                s1 += __shfl_xor_sync(0xffffffffu, s1, 16);
                if (lane < 4) {
                    atomicAdd(&out[bidx * 256 + c],     s0);
                    atomicAdd(&out[bidx * 256 + c + 1], s1);
                }
            }
        }
    }
}

extern "C" void kernel_launch(void* const* d_in, const int* in_sizes, int n_in,
                              void* d_out, int out_size) {
    const float* h0  = (const float*)d_in[0];
    const float* hT  = (const float*)d_in[1];
    const float* gW0 = (const float*)d_in[2];  const float* gb0 = (const float*)d_in[3];
    const float* gW1 = (const float*)d_in[4];  const float* gb1 = (const float*)d_in[5];
    const float* gW2 = (const float*)d_in[6];  const float* gb2 = (const float*)d_in[7];
    const float* gW3 = (const float*)d_in[8];  const float* gb3 = (const float*)d_in[9];
    const float* oW0 = (const float*)d_in[10]; const float* ob0 = (const float*)d_in[11];
    const float* oW1 = (const float*)d_in[12]; const float* ob1 = (const float*)d_in[13];
    const float* oW2 = (const float*)d_in[14]; const float* ob2 = (const float*)d_in[15];
    const float* oW3 = (const float*)d_in[16]; const float* ob3 = (const float*)d_in[17];
    float* out = (float*)d_out;

    cudaFuncSetAttribute(readout_kernel,
                         cudaFuncAttributeMaxDynamicSharedMemorySize, SMEM_BYTES);
    cudaMemsetAsync(d_out, 0, (size_t)out_size * sizeof(float), 0);
    pack_kernel<<<NCHUNK, 256>>>(gW0, gW1, gW2, gW3, oW0, oW1, oW2, oW3);
    readout_kernel<<<2048, THREADS, SMEM_BYTES>>>(
        h0, hT, gb0, gb1, gb2, gb3, ob0, ob1, ob2, ob3, out);
}